// round 14
// baseline (speedup 1.0000x reference)
#include <cuda_runtime.h>
#include <cuda_fp16.h>
#include <cuda_bf16.h>

#define N_NODES   10000
#define N_EDGES   640000
#define F_IN      128
#define H1        64
#define H2        32
#define N_CLASSES 16

// ---------------- scratch (device globals) ----------------------------------
__device__ float g_h1f [N_NODES * H1];       // raw fp32 h1 = x @ W1
__device__ uint4 g_h1s [N_NODES * H1 / 8];   // h1 * dinv[n]  (fp16 payload)
__device__ uint4 g_agg1[N_NODES * H1 / 8];   // fp16 accum: init h1s + b1*rd
__device__ uint4 g_h2s [N_NODES * H2 / 8];   // h2 * dinv[n]  (fp16)
__device__ uint4 g_agg2[N_NODES * H2 / 8];   // fp16 accum: init h2s + b2*rd
__device__ int   g_deg [N_NODES];            // ALWAYS zero at launch entry
__device__ float g_colsum[H2];
__device__ unsigned g_ticket = 0;            // post2 last-block ticket

// 16-byte vectorized fp16 reduction (no return), sm_90+
__device__ __forceinline__ void red_add_v4_f16x2(void* addr, uint4 a) {
    asm volatile("red.global.add.noftz.v4.f16x2 [%0], {%1,%2,%3,%4};"
                 :: "l"(addr), "r"(a.x), "r"(a.y), "r"(a.z), "r"(a.w)
                 : "memory");
}

__device__ __forceinline__ uint2 pack8h(float4 a, float4 b) {
    __half2 p0 = __floats2half2_rn(a.x, a.y);
    __half2 p1 = __floats2half2_rn(a.z, a.w);
    __half2 p2 = __floats2half2_rn(b.x, b.y);
    __half2 p3 = __floats2half2_rn(b.z, b.w);
    // pack into 2x uint2 halves -> caller writes as uint4 via two uint2s
    uint2 r;
    r.x = *(unsigned*)&p0 | 0u; r.y = *(unsigned*)&p1;
    (void)p2; (void)p3;
    return r;
}

// ---------------- degree histogram (+ colsum zero), 2 edges/thread ------------
__global__ void hist_kernel(const int* __restrict__ ei) {
    int t = blockIdx.x * blockDim.x + threadIdx.x;
    if (blockIdx.x == 0 && threadIdx.x < H2) g_colsum[threadIdx.x] = 0.0f;
    if (t >= N_EDGES / 2) return;
    int2 d2 = *(const int2*)(ei + N_EDGES + t * 2);
    atomicAdd(&g_deg[d2.x], 1);
    atomicAdd(&g_deg[d2.y], 1);
}

// ---------------- gemm1_mm: h1f = x @ W1 (fp32, NO deg dependency) -----------
__global__ __launch_bounds__(256) void gemm1_mm(const float* __restrict__ x,
                                                const float* __restrict__ W1) {
    __shared__ float Ws[64][64];
    __shared__ float Xt[64][68];

    const int tid = threadIdx.x;
    const int tx  = tid & 15;
    const int ty  = tid >> 4;
    const int node0 = blockIdx.x * 64;

    float acc[4][4];
#pragma unroll
    for (int i = 0; i < 4; i++)
#pragma unroll
        for (int j = 0; j < 4; j++) acc[i][j] = 0.0f;

    for (int kc = 0; kc < 2; kc++) {
        {
            int r  = tid >> 4;
            int c4 = (tid & 15) * 4;
#pragma unroll
            for (int p = 0; p < 4; p++) {
                int rr = r + p * 16;
                *(float4*)(&Ws[rr][c4]) =
                    *(const float4*)(W1 + (kc * 64 + rr) * H1 + c4);
            }
        }
        {
            int nl = tid & 63;
            int kq = (tid >> 6) * 4;
            int node = node0 + nl;
#pragma unroll
            for (int p = 0; p < 4; p++) {
                int k4 = kq + p * 16;
                float4 v = make_float4(0.f, 0.f, 0.f, 0.f);
                if (node < N_NODES)
                    v = *(const float4*)(x + node * F_IN + kc * 64 + k4);
                Xt[k4 + 0][nl] = v.x; Xt[k4 + 1][nl] = v.y;
                Xt[k4 + 2][nl] = v.z; Xt[k4 + 3][nl] = v.w;
            }
        }
        __syncthreads();

#pragma unroll 8
        for (int k = 0; k < 64; k++) {
            float4 wv = *(const float4*)(&Ws[k][tx * 4]);
            float4 xv = *(const float4*)(&Xt[k][ty * 4]);
            acc[0][0] += xv.x * wv.x; acc[0][1] += xv.x * wv.y;
            acc[0][2] += xv.x * wv.z; acc[0][3] += xv.x * wv.w;
            acc[1][0] += xv.y * wv.x; acc[1][1] += xv.y * wv.y;
            acc[1][2] += xv.y * wv.z; acc[1][3] += xv.y * wv.w;
            acc[2][0] += xv.z * wv.x; acc[2][1] += xv.z * wv.y;
            acc[2][2] += xv.z * wv.z; acc[2][3] += xv.z * wv.w;
            acc[3][0] += xv.w * wv.x; acc[3][1] += xv.w * wv.y;
            acc[3][2] += xv.w * wv.z; acc[3][3] += xv.w * wv.w;
        }
        __syncthreads();
    }

#pragma unroll
    for (int i = 0; i < 4; i++) {
        int node = node0 + ty * 4 + i;
        if (node < N_NODES)
            *(float4*)(g_h1f + node * H1 + tx * 4) =
                make_float4(acc[i][0], acc[i][1], acc[i][2], acc[i][3]);
    }
}

// ---------------- scale1: (h1f, deg) -> h1s fp16, agg1 init fp16 -------------
// 8 threads/node, each handles 8 feats (one uint4 out per buffer).
__global__ void scale1_kernel(const float* __restrict__ b1) {
    int t = blockIdx.x * blockDim.x + threadIdx.x;
    if (t >= N_NODES * 8) return;
    int node = t >> 3;
    int q    = t & 7;
    float dp1 = (float)g_deg[node] + 1.0f;
    float d   = rsqrtf(dp1);
    float rd  = dp1 * d;                      // sqrt(deg+1)

    const float4* hp = (const float4*)(g_h1f + node * H1 + q * 8);
    float4 a = hp[0], b = hp[1];
    float4 b0 = *(const float4*)(b1 + q * 8);
    float4 b1v = *(const float4*)(b1 + q * 8 + 4);

    float4 ha = make_float4(a.x * d, a.y * d, a.z * d, a.w * d);
    float4 hb = make_float4(b.x * d, b.y * d, b.z * d, b.w * d);

    __half2 s0 = __floats2half2_rn(ha.x, ha.y);
    __half2 s1 = __floats2half2_rn(ha.z, ha.w);
    __half2 s2 = __floats2half2_rn(hb.x, hb.y);
    __half2 s3 = __floats2half2_rn(hb.z, hb.w);
    g_h1s[node * 8 + q] = make_uint4(*(unsigned*)&s0, *(unsigned*)&s1,
                                     *(unsigned*)&s2, *(unsigned*)&s3);

    __half2 a0 = __floats2half2_rn(ha.x + b0.x * rd, ha.y + b0.y * rd);
    __half2 a1 = __floats2half2_rn(ha.z + b0.z * rd, ha.w + b0.w * rd);
    __half2 a2 = __floats2half2_rn(hb.x + b1v.x * rd, hb.y + b1v.y * rd);
    __half2 a3 = __floats2half2_rn(hb.z + b1v.z * rd, hb.w + b1v.w * rd);
    g_agg1[node * 8 + q] = make_uint4(*(unsigned*)&a0, *(unsigned*)&a1,
                                      *(unsigned*)&a2, *(unsigned*)&a3);
}

// ---------------- edge aggregation layer 1 -----------------------------------
// 8 threads per edge, 16B fp16 slice each: gather + one v4.f16x2 red.
__global__ void agg1_kernel(const int* __restrict__ ei) {
    long long t = (long long)blockIdx.x * blockDim.x + threadIdx.x;
    int e = (int)(t >> 3);
    int q = (int)(t & 7);
    if (e >= N_EDGES) return;
    int src = __ldg(&ei[e]);
    int dst = __ldg(&ei[N_EDGES + e]);
    uint4 a = g_h1s[src * 8 + q];
    red_add_v4_f16x2(g_agg1 + dst * 8 + q, a);
}

// ---------------- gemm2: h2 = relu(agg1*d) @ W2 ------------------------------
// 32 nodes x 32 outs, 128 threads, micro 2x4, grid 313.
__global__ __launch_bounds__(128) void gemm2_kernel(const float* __restrict__ W2,
                                                    const float* __restrict__ b2) {
    __shared__ float Ws[64][32];
    __shared__ float Xt[64][36];

    const int tid = threadIdx.x;
    const int tx  = tid & 7;
    const int ty  = tid >> 3;
    const int node0 = blockIdx.x * 32;

    {
        int r  = tid >> 3;
        int c4 = (tid & 7) * 4;
#pragma unroll
        for (int p = 0; p < 4; p++) {
            int rr = r + p * 16;
            *(float4*)(&Ws[rr][c4]) = *(const float4*)(W2 + rr * H2 + c4);
        }
    }
    {
        int nl = tid & 31;
        int p0 = tid >> 5;
        int node = node0 + nl;
        float d = 0.f;
        if (node < N_NODES) d = rsqrtf((float)g_deg[node] + 1.0f);
#pragma unroll
        for (int pp = 0; pp < 2; pp++) {
            int p = p0 + pp * 4;
            int k8 = p * 8;
            uint4 raw = make_uint4(0, 0, 0, 0);
            if (node < N_NODES)
                raw = g_agg1[node * 8 + p];
            __half2* hp = (__half2*)&raw;
#pragma unroll
            for (int u = 0; u < 4; u++) {
                float2 f = __half22float2(hp[u]);
                Xt[k8 + u * 2 + 0][nl] = fmaxf(f.x * d, 0.f);
                Xt[k8 + u * 2 + 1][nl] = fmaxf(f.y * d, 0.f);
            }
        }
    }
    __syncthreads();

    float acc[2][4];
#pragma unroll
    for (int i = 0; i < 2; i++)
#pragma unroll
        for (int j = 0; j < 4; j++) acc[i][j] = 0.0f;

#pragma unroll 8
    for (int k = 0; k < 64; k++) {
        float4 wv = *(const float4*)(&Ws[k][tx * 4]);
        float x0 = Xt[k][ty * 2 + 0];
        float x1 = Xt[k][ty * 2 + 1];
        acc[0][0] += x0 * wv.x; acc[0][1] += x0 * wv.y;
        acc[0][2] += x0 * wv.z; acc[0][3] += x0 * wv.w;
        acc[1][0] += x1 * wv.x; acc[1][1] += x1 * wv.y;
        acc[1][2] += x1 * wv.z; acc[1][3] += x1 * wv.w;
    }

    float4 bv = *(const float4*)(b2 + tx * 4);
#pragma unroll
    for (int i = 0; i < 2; i++) {
        int node = node0 + ty * 2 + i;
        if (node < N_NODES) {
            float dp1 = (float)g_deg[node] + 1.0f;
            float d   = rsqrtf(dp1);
            float rd  = dp1 * d;
            float4 hs = make_float4(acc[i][0] * d, acc[i][1] * d,
                                    acc[i][2] * d, acc[i][3] * d);
            __half2 hp0 = __floats2half2_rn(hs.x, hs.y);
            __half2 hp1 = __floats2half2_rn(hs.z, hs.w);
            *(uint2*)((__half*)g_h2s + node * H2 + tx * 4) =
                make_uint2(*(unsigned*)&hp0, *(unsigned*)&hp1);
            __half2 ap0 = __floats2half2_rn(hs.x + bv.x * rd, hs.y + bv.y * rd);
            __half2 ap1 = __floats2half2_rn(hs.z + bv.z * rd, hs.w + bv.w * rd);
            *(uint2*)((__half*)g_agg2 + node * H2 + tx * 4) =
                make_uint2(*(unsigned*)&ap0, *(unsigned*)&ap1);
        }
    }
}

// ---------------- edge aggregation layer 2 -----------------------------------
__global__ void agg2_kernel(const int* __restrict__ ei) {
    long long t = (long long)blockIdx.x * blockDim.x + threadIdx.x;
    int e = (int)(t >> 2);
    int q = (int)(t & 3);
    if (e >= N_EDGES) return;
    int src = __ldg(&ei[e]);
    int dst = __ldg(&ei[N_EDGES + e]);
    uint4 a = g_h2s[src * 4 + q];
    red_add_v4_f16x2(g_agg2 + dst * 4 + q, a);
}

// ---------------- post2 + final (last-block) ----------------------------------
// relu(agg2*d) + mean-pool colsum; last block computes output and resets state.
__global__ void post2_kernel(const float* __restrict__ Wfc,
                             const float* __restrict__ bfc,
                             float* __restrict__ out) {
    __shared__ float s[512];
    __shared__ bool last;
    int t = blockIdx.x * blockDim.x + threadIdx.x;   // over N_NODES*16
    float v0 = 0.0f, v1 = 0.0f;
    if (t < N_NODES * 16) {
        int n = t >> 4;
        float d = rsqrtf((float)g_deg[n] + 1.0f);
        unsigned raw = ((const unsigned*)g_agg2)[t];
        float2 f = __half22float2(*(__half2*)&raw);
        v0 = fmaxf(f.x * d, 0.0f);
        v1 = fmaxf(f.y * d, 0.0f);
    }
    s[threadIdx.x * 2 + 0] = v0;
    s[threadIdx.x * 2 + 1] = v1;
    __syncthreads();
#pragma unroll
    for (int st = 128; st >= 16; st >>= 1) {
        if (threadIdx.x < st) {
            s[threadIdx.x * 2 + 0] += s[(threadIdx.x + st) * 2 + 0];
            s[threadIdx.x * 2 + 1] += s[(threadIdx.x + st) * 2 + 1];
        }
        __syncthreads();
    }
    if (threadIdx.x < 16) {
        atomicAdd(&g_colsum[threadIdx.x * 2 + 0], s[threadIdx.x * 2 + 0]);
        atomicAdd(&g_colsum[threadIdx.x * 2 + 1], s[threadIdx.x * 2 + 1]);
    }
    __threadfence();
    if (threadIdx.x == 0)
        last = (atomicAdd(&g_ticket, 1u) == gridDim.x - 1);
    __syncthreads();
    if (last) {
        __threadfence();                       // acquire: see all colsum adds
        // reset deg for next replay (all consumers done)
        for (int i = threadIdx.x; i < N_NODES; i += blockDim.x) g_deg[i] = 0;
        if (threadIdx.x < N_CLASSES) {
            int c = threadIdx.x;
            float acc = bfc[c];
            const float inv_n = 1.0f / (float)N_NODES;
#pragma unroll
            for (int f = 0; f < H2; f++)
                acc += (__ldcg(&g_colsum[f]) * inv_n) * Wfc[f * N_CLASSES + c];
            out[c] = acc;
        }
        if (threadIdx.x == 0) g_ticket = 0;    // reset ticket for next replay
    }
}

// ---------------- launch ------------------------------------------------------
static cudaStream_t side_stream() {
    static cudaStream_t s = [] {
        cudaStream_t st;
        cudaStreamCreateWithFlags(&st, cudaStreamNonBlocking);
        return st;
    }();
    return s;
}
static cudaEvent_t ev(int i) {
    static cudaEvent_t e[2] = { [] { cudaEvent_t x;
        cudaEventCreateWithFlags(&x, cudaEventDisableTiming); return x; }(),
                                [] { cudaEvent_t x;
        cudaEventCreateWithFlags(&x, cudaEventDisableTiming); return x; }() };
    return e[i];
}

extern "C" void kernel_launch(void* const* d_in, const int* in_sizes, int n_in,
                              void* d_out, int out_size) {
    const float* x   = (const float*)d_in[0];
    const float* W1  = (const float*)d_in[1];
    const float* b1  = (const float*)d_in[2];
    const float* W2  = (const float*)d_in[3];
    const float* b2  = (const float*)d_in[4];
    const float* Wfc = (const float*)d_in[5];
    const float* bfc = (const float*)d_in[6];
    const int*   ei  = (const int*)  d_in[7];
    float* out = (float*)d_out;

    cudaStream_t s1 = side_stream();
    cudaEvent_t e0 = ev(0), e1 = ev(1);

    // fork: hist on side stream, concurrent with gemm1_mm on main stream
    cudaEventRecord(e0, 0);
    cudaStreamWaitEvent(s1, e0, 0);
    hist_kernel<<<N_EDGES / 2 / 256, 256, 0, s1>>>(ei);
    cudaEventRecord(e1, s1);

    gemm1_mm<<<(N_NODES + 63) / 64, 256>>>(x, W1);

    // join: scale1 needs both h1f (main) and deg (side)
    cudaStreamWaitEvent(0, e1, 0);
    scale1_kernel<<<(N_NODES * 8 + 255) / 256, 256>>>(b1);

    agg1_kernel<<<N_EDGES * 8 / 256, 256>>>(ei);

    gemm2_kernel<<<(N_NODES + 31) / 32, 128>>>(W2, b2);
    agg2_kernel<<<N_EDGES * 4 / 256, 256>>>(ei);

    post2_kernel<<<(N_NODES * 16 + 255) / 256, 256>>>(Wfc, bfc, out);
}

// round 15
// speedup vs baseline: 1.1593x; 1.1593x over previous
#include <cuda_runtime.h>
#include <cuda_fp16.h>
#include <cuda_bf16.h>

#define N_NODES   10000
#define N_EDGES   640000
#define F_IN      128
#define H1        64
#define H2        32
#define N_CLASSES 16

// ---------------- scratch (device globals) ----------------------------------
__device__ uint4 g_h1s [N_NODES * H1 / 8];   // h1 * dinv[n]  (fp16 payload)
__device__ uint4 g_agg1[N_NODES * H1 / 8];   // fp16 accum: init h1s + b1*rd
__device__ uint4 g_h2s [N_NODES * H2 / 8];   // h2 * dinv[n]  (fp16)
__device__ uint4 g_agg2[N_NODES * H2 / 8];   // fp16 accum: init h2s + b2*rd
__device__ int   g_deg [N_NODES];            // ALWAYS zero at launch entry
__device__ float g_colsum[H2];
__device__ unsigned g_ticket = 0;            // post2 last-block ticket

// 16-byte vectorized fp16 reduction (no return), sm_90+
__device__ __forceinline__ void red_add_v4_f16x2(void* addr, uint4 a) {
    asm volatile("red.global.add.noftz.v4.f16x2 [%0], {%1,%2,%3,%4};"
                 :: "l"(addr), "r"(a.x), "r"(a.y), "r"(a.z), "r"(a.w)
                 : "memory");
}

// ---------------- degree histogram (+ colsum zero), 2 edges/thread ------------
__global__ void hist_kernel(const int* __restrict__ ei) {
    int t = blockIdx.x * blockDim.x + threadIdx.x;
    if (blockIdx.x == 0 && threadIdx.x < H2) g_colsum[threadIdx.x] = 0.0f;
    if (t >= N_EDGES / 2) return;
    int2 d2 = *(const int2*)(ei + N_EDGES + t * 2);
    atomicAdd(&g_deg[d2.x], 1);
    atomicAdd(&g_deg[d2.y], 1);
}

// ---------------- gemm1: h1 = x @ W1 -----------------------------------------
// 64 nodes x 64 outs, 256 threads, micro 4x4, two K chunks of 64.
// epilogue (fp16): h1s = h1*d;  agg1 = h1s + b1*rd  (true act = relu(agg1*d))
__global__ __launch_bounds__(256) void gemm1_kernel(const float* __restrict__ x,
                                                    const float* __restrict__ W1,
                                                    const float* __restrict__ b1) {
    __shared__ float Ws[64][64];
    __shared__ float Xt[64][68];

    const int tid = threadIdx.x;
    const int tx  = tid & 15;
    const int ty  = tid >> 4;
    const int node0 = blockIdx.x * 64;

    float acc[4][4];
#pragma unroll
    for (int i = 0; i < 4; i++)
#pragma unroll
        for (int j = 0; j < 4; j++) acc[i][j] = 0.0f;

    for (int kc = 0; kc < 2; kc++) {
        {
            int r  = tid >> 4;
            int c4 = (tid & 15) * 4;
#pragma unroll
            for (int p = 0; p < 4; p++) {
                int rr = r + p * 16;
                *(float4*)(&Ws[rr][c4]) =
                    *(const float4*)(W1 + (kc * 64 + rr) * H1 + c4);
            }
        }
        {
            int nl = tid & 63;
            int kq = (tid >> 6) * 4;
            int node = node0 + nl;
#pragma unroll
            for (int p = 0; p < 4; p++) {
                int k4 = kq + p * 16;
                float4 v = make_float4(0.f, 0.f, 0.f, 0.f);
                if (node < N_NODES)
                    v = *(const float4*)(x + node * F_IN + kc * 64 + k4);
                Xt[k4 + 0][nl] = v.x; Xt[k4 + 1][nl] = v.y;
                Xt[k4 + 2][nl] = v.z; Xt[k4 + 3][nl] = v.w;
            }
        }
        __syncthreads();

#pragma unroll 8
        for (int k = 0; k < 64; k++) {
            float4 wv = *(const float4*)(&Ws[k][tx * 4]);
            float4 xv = *(const float4*)(&Xt[k][ty * 4]);
            acc[0][0] += xv.x * wv.x; acc[0][1] += xv.x * wv.y;
            acc[0][2] += xv.x * wv.z; acc[0][3] += xv.x * wv.w;
            acc[1][0] += xv.y * wv.x; acc[1][1] += xv.y * wv.y;
            acc[1][2] += xv.y * wv.z; acc[1][3] += xv.y * wv.w;
            acc[2][0] += xv.z * wv.x; acc[2][1] += xv.z * wv.y;
            acc[2][2] += xv.z * wv.z; acc[2][3] += xv.z * wv.w;
            acc[3][0] += xv.w * wv.x; acc[3][1] += xv.w * wv.y;
            acc[3][2] += xv.w * wv.z; acc[3][3] += xv.w * wv.w;
        }
        __syncthreads();
    }

    float4 bv = *(const float4*)(b1 + tx * 4);
#pragma unroll
    for (int i = 0; i < 4; i++) {
        int node = node0 + ty * 4 + i;
        if (node < N_NODES) {
            float dp1 = (float)g_deg[node] + 1.0f;
            float d   = rsqrtf(dp1);
            float rd  = dp1 * d;              // sqrt(deg+1)
            float4 hs = make_float4(acc[i][0] * d, acc[i][1] * d,
                                    acc[i][2] * d, acc[i][3] * d);
            __half2 hp0 = __floats2half2_rn(hs.x, hs.y);
            __half2 hp1 = __floats2half2_rn(hs.z, hs.w);
            *(uint2*)((__half*)g_h1s + node * H1 + tx * 4) =
                make_uint2(*(unsigned*)&hp0, *(unsigned*)&hp1);
            __half2 ap0 = __floats2half2_rn(hs.x + bv.x * rd, hs.y + bv.y * rd);
            __half2 ap1 = __floats2half2_rn(hs.z + bv.z * rd, hs.w + bv.w * rd);
            *(uint2*)((__half*)g_agg1 + node * H1 + tx * 4) =
                make_uint2(*(unsigned*)&ap0, *(unsigned*)&ap1);
        }
    }
}

// ---------------- edge aggregation layer 1 -----------------------------------
// 8 threads per edge, 16B fp16 slice each: gather + one v4.f16x2 red.
__global__ void agg1_kernel(const int* __restrict__ ei) {
    long long t = (long long)blockIdx.x * blockDim.x + threadIdx.x;
    int e = (int)(t >> 3);
    int q = (int)(t & 7);
    if (e >= N_EDGES) return;
    int src = __ldg(&ei[e]);
    int dst = __ldg(&ei[N_EDGES + e]);
    uint4 a = g_h1s[src * 8 + q];                // 8 uint4 per 64-half row
    red_add_v4_f16x2(g_agg1 + dst * 8 + q, a);
}

// ---------------- gemm2: h2 = relu(agg1*d) @ W2 ------------------------------
// 64 nodes x 32 outs, 128 threads, micro 4x4; fp16 agg1 -> fp32 smem with
// deferred dinv + relu. epilogue (fp16): h2s = h2*d; agg2 = h2s + b2*rd.
__global__ __launch_bounds__(128) void gemm2_kernel(const float* __restrict__ W2,
                                                    const float* __restrict__ b2) {
    __shared__ float Ws[64][32];
    __shared__ float Xt[64][68];

    const int tid = threadIdx.x;
    const int tx  = tid & 7;
    const int ty  = tid >> 3;
    const int node0 = blockIdx.x * 64;

    {
        int r  = tid >> 3;
        int c4 = (tid & 7) * 4;
#pragma unroll
        for (int p = 0; p < 4; p++) {
            int rr = r + p * 16;
            *(float4*)(&Ws[rr][c4]) = *(const float4*)(W2 + rr * H2 + c4);
        }
    }
    {
        int nl = tid & 63;                 // node local
        int hsel = tid >> 6;               // 0/1 -> k half [0,32) or [32,64)
        int node = node0 + nl;
        float d = 0.f;
        if (node < N_NODES) d = rsqrtf((float)g_deg[node] + 1.0f);
#pragma unroll
        for (int p = 0; p < 4; p++) {
            int k8 = hsel * 32 + p * 8;
            uint4 raw = make_uint4(0, 0, 0, 0);
            if (node < N_NODES)
                raw = g_agg1[node * 8 + hsel * 4 + p];
            __half2* hp = (__half2*)&raw;
#pragma unroll
            for (int u = 0; u < 4; u++) {
                float2 f = __half22float2(hp[u]);
                Xt[k8 + u * 2 + 0][nl] = fmaxf(f.x * d, 0.f);
                Xt[k8 + u * 2 + 1][nl] = fmaxf(f.y * d, 0.f);
            }
        }
    }
    __syncthreads();

    float acc[4][4];
#pragma unroll
    for (int i = 0; i < 4; i++)
#pragma unroll
        for (int j = 0; j < 4; j++) acc[i][j] = 0.0f;

#pragma unroll 8
    for (int k = 0; k < 64; k++) {
        float4 wv = *(const float4*)(&Ws[k][tx * 4]);
        float4 xv = *(const float4*)(&Xt[k][ty * 4]);
        acc[0][0] += xv.x * wv.x; acc[0][1] += xv.x * wv.y;
        acc[0][2] += xv.x * wv.z; acc[0][3] += xv.x * wv.w;
        acc[1][0] += xv.y * wv.x; acc[1][1] += xv.y * wv.y;
        acc[1][2] += xv.y * wv.z; acc[1][3] += xv.y * wv.w;
        acc[2][0] += xv.z * wv.x; acc[2][1] += xv.z * wv.y;
        acc[2][2] += xv.z * wv.z; acc[2][3] += xv.z * wv.w;
        acc[3][0] += xv.w * wv.x; acc[3][1] += xv.w * wv.y;
        acc[3][2] += xv.w * wv.z; acc[3][3] += xv.w * wv.w;
    }

    float4 bv = *(const float4*)(b2 + tx * 4);
#pragma unroll
    for (int i = 0; i < 4; i++) {
        int node = node0 + ty * 4 + i;
        if (node < N_NODES) {
            float dp1 = (float)g_deg[node] + 1.0f;
            float d   = rsqrtf(dp1);
            float rd  = dp1 * d;
            float4 hs = make_float4(acc[i][0] * d, acc[i][1] * d,
                                    acc[i][2] * d, acc[i][3] * d);
            __half2 hp0 = __floats2half2_rn(hs.x, hs.y);
            __half2 hp1 = __floats2half2_rn(hs.z, hs.w);
            *(uint2*)((__half*)g_h2s + node * H2 + tx * 4) =
                make_uint2(*(unsigned*)&hp0, *(unsigned*)&hp1);
            __half2 ap0 = __floats2half2_rn(hs.x + bv.x * rd, hs.y + bv.y * rd);
            __half2 ap1 = __floats2half2_rn(hs.z + bv.z * rd, hs.w + bv.w * rd);
            *(uint2*)((__half*)g_agg2 + node * H2 + tx * 4) =
                make_uint2(*(unsigned*)&ap0, *(unsigned*)&ap1);
        }
    }
}

// ---------------- edge aggregation layer 2 -----------------------------------
// 4 threads per edge, 16B fp16 slice each: gather + one v4.f16x2 red.
__global__ void agg2_kernel(const int* __restrict__ ei) {
    long long t = (long long)blockIdx.x * blockDim.x + threadIdx.x;
    int e = (int)(t >> 2);
    int q = (int)(t & 3);
    if (e >= N_EDGES) return;
    int src = __ldg(&ei[e]);
    int dst = __ldg(&ei[N_EDGES + e]);
    uint4 a = g_h2s[src * 4 + q];                // 4 uint4 per 32-half row
    red_add_v4_f16x2(g_agg2 + dst * 4 + q, a);
}

// ---------------- post2 + final (last-block pattern) ---------------------------
// relu(agg2*d) + mean-pool colsum; last block computes output + resets state.
__global__ void post2_kernel(const float* __restrict__ Wfc,
                             const float* __restrict__ bfc,
                             float* __restrict__ out) {
    __shared__ float s[512];
    __shared__ bool last;
    int t = blockIdx.x * blockDim.x + threadIdx.x;   // over N_NODES*16
    float v0 = 0.0f, v1 = 0.0f;
    if (t < N_NODES * 16) {
        int n = t >> 4;
        float d = rsqrtf((float)g_deg[n] + 1.0f);
        unsigned raw = ((const unsigned*)g_agg2)[t];   // 2 halves
        float2 f = __half22float2(*(__half2*)&raw);
        v0 = fmaxf(f.x * d, 0.0f);
        v1 = fmaxf(f.y * d, 0.0f);
    }
    s[threadIdx.x * 2 + 0] = v0;
    s[threadIdx.x * 2 + 1] = v1;
    __syncthreads();
#pragma unroll
    for (int st = 128; st >= 16; st >>= 1) {
        if (threadIdx.x < st) {
            s[threadIdx.x * 2 + 0] += s[(threadIdx.x + st) * 2 + 0];
            s[threadIdx.x * 2 + 1] += s[(threadIdx.x + st) * 2 + 1];
        }
        __syncthreads();
    }
    if (threadIdx.x < 16) {
        atomicAdd(&g_colsum[threadIdx.x * 2 + 0], s[threadIdx.x * 2 + 0]);
        atomicAdd(&g_colsum[threadIdx.x * 2 + 1], s[threadIdx.x * 2 + 1]);
    }
    __threadfence();
    if (threadIdx.x == 0)
        last = (atomicAdd(&g_ticket, 1u) == gridDim.x - 1);
    __syncthreads();
    if (last) {
        __threadfence();                       // acquire: see all colsum adds
        for (int i = threadIdx.x; i < N_NODES; i += blockDim.x) g_deg[i] = 0;
        if (threadIdx.x < N_CLASSES) {
            int c = threadIdx.x;
            float acc = bfc[c];
            const float inv_n = 1.0f / (float)N_NODES;
#pragma unroll
            for (int f = 0; f < H2; f++)
                acc += (__ldcg(&g_colsum[f]) * inv_n) * Wfc[f * N_CLASSES + c];
            out[c] = acc;
        }
        if (threadIdx.x == 0) g_ticket = 0;    // reset ticket for next replay
    }
}

// ---------------- launch ------------------------------------------------------
extern "C" void kernel_launch(void* const* d_in, const int* in_sizes, int n_in,
                              void* d_out, int out_size) {
    const float* x   = (const float*)d_in[0];
    const float* W1  = (const float*)d_in[1];
    const float* b1  = (const float*)d_in[2];
    const float* W2  = (const float*)d_in[3];
    const float* b2  = (const float*)d_in[4];
    const float* Wfc = (const float*)d_in[5];
    const float* bfc = (const float*)d_in[6];
    const int*   ei  = (const int*)  d_in[7];
    float* out = (float*)d_out;

    hist_kernel<<<N_EDGES / 2 / 256, 256>>>(ei);

    gemm1_kernel<<<(N_NODES + 63) / 64, 256>>>(x, W1, b1);
    agg1_kernel<<<N_EDGES * 8 / 256, 256>>>(ei);

    gemm2_kernel<<<(N_NODES + 63) / 64, 128>>>(W2, b2);
    agg2_kernel<<<N_EDGES * 4 / 256, 256>>>(ei);

    post2_kernel<<<(N_NODES * 16 + 255) / 256, 256>>>(Wfc, bfc, out);
}

// round 16
// speedup vs baseline: 1.1712x; 1.0102x over previous
#include <cuda_runtime.h>
#include <cuda_fp16.h>
#include <cuda_bf16.h>

#define N_NODES   10000
#define N_EDGES   640000
#define F_IN      128
#define H1        64
#define H2        32
#define N_CLASSES 16

// ---------------- scratch (device globals) ----------------------------------
__device__ uint4 g_h1s [N_NODES * H1 / 8];   // h1 * dinv[n]  (fp16 payload)
__device__ uint4 g_agg1[N_NODES * H1 / 8];   // fp16 accum: init h1s + b1*rd
__device__ uint4 g_h2s [N_NODES * H2 / 8];   // h2 * dinv[n]  (fp16)
__device__ uint4 g_agg2[N_NODES * H2 / 8];   // fp16 accum: init h2s + b2*rd
__device__ int   g_deg [N_NODES];            // ALWAYS zero at launch entry
__device__ float g_colsum[H2];
__device__ unsigned g_ticket = 0;            // post2 last-block ticket

// 16-byte vectorized fp16 reduction (no return), sm_90+
__device__ __forceinline__ void red_add_v4_f16x2(void* addr, uint4 a) {
    asm volatile("red.global.add.noftz.v4.f16x2 [%0], {%1,%2,%3,%4};"
                 :: "l"(addr), "r"(a.x), "r"(a.y), "r"(a.z), "r"(a.w)
                 : "memory");
}

// ---------------- degree histogram (+ colsum zero), 2 edges/thread ------------
__global__ void hist_kernel(const int* __restrict__ ei) {
    int t = blockIdx.x * blockDim.x + threadIdx.x;
    if (blockIdx.x == 0 && threadIdx.x < H2) g_colsum[threadIdx.x] = 0.0f;
    if (t >= N_EDGES / 2) return;
    int2 d2 = *(const int2*)(ei + N_EDGES + t * 2);
    atomicAdd(&g_deg[d2.x], 1);
    atomicAdd(&g_deg[d2.y], 1);
}

// ---------------- gemm1: h1 = x @ W1 -----------------------------------------
// 64 nodes x 64 outs, 256 threads, micro 4x4, two K chunks of 64.
// epilogue (fp16): h1s = h1*d;  agg1 = h1s + b1*rd  (true act = relu(agg1*d))
__global__ __launch_bounds__(256) void gemm1_kernel(const float* __restrict__ x,
                                                    const float* __restrict__ W1,
                                                    const float* __restrict__ b1) {
    __shared__ float Ws[64][64];
    __shared__ float Xt[64][68];

    const int tid = threadIdx.x;
    const int tx  = tid & 15;
    const int ty  = tid >> 4;
    const int node0 = blockIdx.x * 64;

    float acc[4][4];
#pragma unroll
    for (int i = 0; i < 4; i++)
#pragma unroll
        for (int j = 0; j < 4; j++) acc[i][j] = 0.0f;

    for (int kc = 0; kc < 2; kc++) {
        {
            int r  = tid >> 4;
            int c4 = (tid & 15) * 4;
#pragma unroll
            for (int p = 0; p < 4; p++) {
                int rr = r + p * 16;
                *(float4*)(&Ws[rr][c4]) =
                    *(const float4*)(W1 + (kc * 64 + rr) * H1 + c4);
            }
        }
        {
            int nl = tid & 63;
            int kq = (tid >> 6) * 4;
            int node = node0 + nl;
#pragma unroll
            for (int p = 0; p < 4; p++) {
                int k4 = kq + p * 16;
                float4 v = make_float4(0.f, 0.f, 0.f, 0.f);
                if (node < N_NODES)
                    v = *(const float4*)(x + node * F_IN + kc * 64 + k4);
                Xt[k4 + 0][nl] = v.x; Xt[k4 + 1][nl] = v.y;
                Xt[k4 + 2][nl] = v.z; Xt[k4 + 3][nl] = v.w;
            }
        }
        __syncthreads();

#pragma unroll 8
        for (int k = 0; k < 64; k++) {
            float4 wv = *(const float4*)(&Ws[k][tx * 4]);
            float4 xv = *(const float4*)(&Xt[k][ty * 4]);
            acc[0][0] += xv.x * wv.x; acc[0][1] += xv.x * wv.y;
            acc[0][2] += xv.x * wv.z; acc[0][3] += xv.x * wv.w;
            acc[1][0] += xv.y * wv.x; acc[1][1] += xv.y * wv.y;
            acc[1][2] += xv.y * wv.z; acc[1][3] += xv.y * wv.w;
            acc[2][0] += xv.z * wv.x; acc[2][1] += xv.z * wv.y;
            acc[2][2] += xv.z * wv.z; acc[2][3] += xv.z * wv.w;
            acc[3][0] += xv.w * wv.x; acc[3][1] += xv.w * wv.y;
            acc[3][2] += xv.w * wv.z; acc[3][3] += xv.w * wv.w;
        }
        __syncthreads();
    }

    float4 bv = *(const float4*)(b1 + tx * 4);
#pragma unroll
    for (int i = 0; i < 4; i++) {
        int node = node0 + ty * 4 + i;
        if (node < N_NODES) {
            float dp1 = (float)g_deg[node] + 1.0f;
            float d   = rsqrtf(dp1);
            float rd  = dp1 * d;              // sqrt(deg+1)
            float4 hs = make_float4(acc[i][0] * d, acc[i][1] * d,
                                    acc[i][2] * d, acc[i][3] * d);
            __half2 hp0 = __floats2half2_rn(hs.x, hs.y);
            __half2 hp1 = __floats2half2_rn(hs.z, hs.w);
            *(uint2*)((__half*)g_h1s + node * H1 + tx * 4) =
                make_uint2(*(unsigned*)&hp0, *(unsigned*)&hp1);
            __half2 ap0 = __floats2half2_rn(hs.x + bv.x * rd, hs.y + bv.y * rd);
            __half2 ap1 = __floats2half2_rn(hs.z + bv.z * rd, hs.w + bv.w * rd);
            *(uint2*)((__half*)g_agg1 + node * H1 + tx * 4) =
                make_uint2(*(unsigned*)&ap0, *(unsigned*)&ap1);
        }
    }
}

// ---------------- edge aggregation layer 1 -----------------------------------
// Thread handles slice q of TWO consecutive edges: int2 index loads, 2
// independent gathers, 2 REDs to DIFFERENT dst rows (no same-slice serialization).
__global__ void agg1_kernel(const int* __restrict__ ei) {
    long long t = (long long)blockIdx.x * blockDim.x + threadIdx.x;
    int ep = (int)(t >> 3);          // edge pair
    int q  = (int)(t & 7);
    if (ep >= N_EDGES / 2) return;
    int2 s2 = *(const int2*)(ei + ep * 2);             // src[e0], src[e1]
    int2 d2 = *(const int2*)(ei + N_EDGES + ep * 2);   // dst[e0], dst[e1]
    uint4 a0 = g_h1s[s2.x * 8 + q];
    uint4 a1 = g_h1s[s2.y * 8 + q];
    red_add_v4_f16x2(g_agg1 + d2.x * 8 + q, a0);
    red_add_v4_f16x2(g_agg1 + d2.y * 8 + q, a1);
}

// ---------------- gemm2: h2 = relu(agg1*d) @ W2 ------------------------------
// 64 nodes x 32 outs, 128 threads, micro 4x4; fp16 agg1 -> fp32 smem with
// deferred dinv + relu. epilogue (fp16): h2s = h2*d; agg2 = h2s + b2*rd.
__global__ __launch_bounds__(128) void gemm2_kernel(const float* __restrict__ W2,
                                                    const float* __restrict__ b2) {
    __shared__ float Ws[64][32];
    __shared__ float Xt[64][68];

    const int tid = threadIdx.x;
    const int tx  = tid & 7;
    const int ty  = tid >> 3;
    const int node0 = blockIdx.x * 64;

    {
        int r  = tid >> 3;
        int c4 = (tid & 7) * 4;
#pragma unroll
        for (int p = 0; p < 4; p++) {
            int rr = r + p * 16;
            *(float4*)(&Ws[rr][c4]) = *(const float4*)(W2 + rr * H2 + c4);
        }
    }
    {
        int nl = tid & 63;                 // node local
        int hsel = tid >> 6;               // 0/1 -> k half [0,32) or [32,64)
        int node = node0 + nl;
        float d = 0.f;
        if (node < N_NODES) d = rsqrtf((float)g_deg[node] + 1.0f);
#pragma unroll
        for (int p = 0; p < 4; p++) {
            int k8 = hsel * 32 + p * 8;
            uint4 raw = make_uint4(0, 0, 0, 0);
            if (node < N_NODES)
                raw = g_agg1[node * 8 + hsel * 4 + p];
            __half2* hp = (__half2*)&raw;
#pragma unroll
            for (int u = 0; u < 4; u++) {
                float2 f = __half22float2(hp[u]);
                Xt[k8 + u * 2 + 0][nl] = fmaxf(f.x * d, 0.f);
                Xt[k8 + u * 2 + 1][nl] = fmaxf(f.y * d, 0.f);
            }
        }
    }
    __syncthreads();

    float acc[4][4];
#pragma unroll
    for (int i = 0; i < 4; i++)
#pragma unroll
        for (int j = 0; j < 4; j++) acc[i][j] = 0.0f;

#pragma unroll 8
    for (int k = 0; k < 64; k++) {
        float4 wv = *(const float4*)(&Ws[k][tx * 4]);
        float4 xv = *(const float4*)(&Xt[k][ty * 4]);
        acc[0][0] += xv.x * wv.x; acc[0][1] += xv.x * wv.y;
        acc[0][2] += xv.x * wv.z; acc[0][3] += xv.x * wv.w;
        acc[1][0] += xv.y * wv.x; acc[1][1] += xv.y * wv.y;
        acc[1][2] += xv.y * wv.z; acc[1][3] += xv.y * wv.w;
        acc[2][0] += xv.z * wv.x; acc[2][1] += xv.z * wv.y;
        acc[2][2] += xv.z * wv.z; acc[2][3] += xv.z * wv.w;
        acc[3][0] += xv.w * wv.x; acc[3][1] += xv.w * wv.y;
        acc[3][2] += xv.w * wv.z; acc[3][3] += xv.w * wv.w;
    }

    float4 bv = *(const float4*)(b2 + tx * 4);
#pragma unroll
    for (int i = 0; i < 4; i++) {
        int node = node0 + ty * 4 + i;
        if (node < N_NODES) {
            float dp1 = (float)g_deg[node] + 1.0f;
            float d   = rsqrtf(dp1);
            float rd  = dp1 * d;
            float4 hs = make_float4(acc[i][0] * d, acc[i][1] * d,
                                    acc[i][2] * d, acc[i][3] * d);
            __half2 hp0 = __floats2half2_rn(hs.x, hs.y);
            __half2 hp1 = __floats2half2_rn(hs.z, hs.w);
            *(uint2*)((__half*)g_h2s + node * H2 + tx * 4) =
                make_uint2(*(unsigned*)&hp0, *(unsigned*)&hp1);
            __half2 ap0 = __floats2half2_rn(hs.x + bv.x * rd, hs.y + bv.y * rd);
            __half2 ap1 = __floats2half2_rn(hs.z + bv.z * rd, hs.w + bv.w * rd);
            *(uint2*)((__half*)g_agg2 + node * H2 + tx * 4) =
                make_uint2(*(unsigned*)&ap0, *(unsigned*)&ap1);
        }
    }
}

// ---------------- edge aggregation layer 2 -----------------------------------
// Thread handles slice q of TWO consecutive edges (same pattern as agg1).
__global__ void agg2_kernel(const int* __restrict__ ei) {
    long long t = (long long)blockIdx.x * blockDim.x + threadIdx.x;
    int ep = (int)(t >> 2);          // edge pair
    int q  = (int)(t & 3);
    if (ep >= N_EDGES / 2) return;
    int2 s2 = *(const int2*)(ei + ep * 2);
    int2 d2 = *(const int2*)(ei + N_EDGES + ep * 2);
    uint4 a0 = g_h2s[s2.x * 4 + q];
    uint4 a1 = g_h2s[s2.y * 4 + q];
    red_add_v4_f16x2(g_agg2 + d2.x * 4 + q, a0);
    red_add_v4_f16x2(g_agg2 + d2.y * 4 + q, a1);
}

// ---------------- post2 + final (last-block pattern) ---------------------------
// relu(agg2*d) + mean-pool colsum; last block computes output + resets state.
__global__ void post2_kernel(const float* __restrict__ Wfc,
                             const float* __restrict__ bfc,
                             float* __restrict__ out) {
    __shared__ float s[512];
    __shared__ bool last;
    int t = blockIdx.x * blockDim.x + threadIdx.x;   // over N_NODES*16
    float v0 = 0.0f, v1 = 0.0f;
    if (t < N_NODES * 16) {
        int n = t >> 4;
        float d = rsqrtf((float)g_deg[n] + 1.0f);
        unsigned raw = ((const unsigned*)g_agg2)[t];   // 2 halves
        float2 f = __half22float2(*(__half2*)&raw);
        v0 = fmaxf(f.x * d, 0.0f);
        v1 = fmaxf(f.y * d, 0.0f);
    }
    s[threadIdx.x * 2 + 0] = v0;
    s[threadIdx.x * 2 + 1] = v1;
    __syncthreads();
#pragma unroll
    for (int st = 128; st >= 16; st >>= 1) {
        if (threadIdx.x < st) {
            s[threadIdx.x * 2 + 0] += s[(threadIdx.x + st) * 2 + 0];
            s[threadIdx.x * 2 + 1] += s[(threadIdx.x + st) * 2 + 1];
        }
        __syncthreads();
    }
    if (threadIdx.x < 16) {
        atomicAdd(&g_colsum[threadIdx.x * 2 + 0], s[threadIdx.x * 2 + 0]);
        atomicAdd(&g_colsum[threadIdx.x * 2 + 1], s[threadIdx.x * 2 + 1]);
    }
    __threadfence();
    if (threadIdx.x == 0)
        last = (atomicAdd(&g_ticket, 1u) == gridDim.x - 1);
    __syncthreads();
    if (last) {
        __threadfence();                       // acquire: see all colsum adds
        for (int i = threadIdx.x; i < N_NODES; i += blockDim.x) g_deg[i] = 0;
        if (threadIdx.x < N_CLASSES) {
            int c = threadIdx.x;
            float acc = bfc[c];
            const float inv_n = 1.0f / (float)N_NODES;
#pragma unroll
            for (int f = 0; f < H2; f++)
                acc += (__ldcg(&g_colsum[f]) * inv_n) * Wfc[f * N_CLASSES + c];
            out[c] = acc;
        }
        if (threadIdx.x == 0) g_ticket = 0;    // reset ticket for next replay
    }
}

// ---------------- launch ------------------------------------------------------
extern "C" void kernel_launch(void* const* d_in, const int* in_sizes, int n_in,
                              void* d_out, int out_size) {
    const float* x   = (const float*)d_in[0];
    const float* W1  = (const float*)d_in[1];
    const float* b1  = (const float*)d_in[2];
    const float* W2  = (const float*)d_in[3];
    const float* b2  = (const float*)d_in[4];
    const float* Wfc = (const float*)d_in[5];
    const float* bfc = (const float*)d_in[6];
    const int*   ei  = (const int*)  d_in[7];
    float* out = (float*)d_out;

    hist_kernel<<<N_EDGES / 2 / 256, 256>>>(ei);

    gemm1_kernel<<<(N_NODES + 63) / 64, 256>>>(x, W1, b1);
    agg1_kernel<<<N_EDGES / 2 * 8 / 256, 256>>>(ei);      // 10000 blocks

    gemm2_kernel<<<(N_NODES + 63) / 64, 128>>>(W2, b2);
    agg2_kernel<<<N_EDGES / 2 * 4 / 256, 256>>>(ei);      // 5000 blocks

    post2_kernel<<<(N_NODES * 16 + 255) / 256, 256>>>(Wfc, bfc, out);
}